// round 11
// baseline (speedup 1.0000x reference)
#include <cuda_runtime.h>
#include <cuda_bf16.h>
#include <cstdint>

// ===========================================================================
// Submanifold 3x3x3 sparse conv, N~1e5, Cin=Cout=64, fp32 in/out.
// mma.sync (m16n8k16 bf16) implicit GEMM, two-term bf16 split:
//   out = sum_k Ahi@Whi + Ahi@Wlo + Alo@Whi      (drop lo*lo, err ~2^-18)
// R11: precomputed neighbor table, 3-stage depth-2 cp.async pipeline,
//      one barrier per tap. Baseline-PTX only (sm_100 target safe).
// ===========================================================================

#define HASH_BITS 18
#define HASH_SIZE (1u << HASH_BITS)
#define HASH_MASK (HASH_SIZE - 1u)
#define MAX_PROBE 4096
#define MAXN      131072
#define MAXTILES  (MAXN / 128)

__device__ unsigned long long g_hkeys[HASH_SIZE];
__device__ int                g_hvals[HASH_SIZE];

// bf16 split features: [MAXN][64] hi, lo
__device__ uint4 g_Ahi4[MAXN * 64 * 2 / 16];
__device__ uint4 g_Alo4[MAXN * 64 * 2 / 16];
// bf16 split transposed weights, PRE-SWIZZLED (SW128): tile k = 64 rows x 128B
__device__ uint4 g_Whi4[27 * 8192 / 16];
__device__ uint4 g_Wlo4[27 * 8192 / 16];
// precomputed neighbor table, tile-major: [tile][tap][row]
__device__ int   g_nbr[MAXTILES * 27 * 128];

__device__ __forceinline__ unsigned hash_mix(unsigned long long z) {
    z ^= z >> 30; z *= 0xbf58476d1ce4e5b9ULL;
    z ^= z >> 27; z *= 0x94d049bb133111ebULL;
    z ^= z >> 31;
    return (unsigned)z & HASH_MASK;
}

__global__ void hash_init_kernel() {
    unsigned i = blockIdx.x * blockDim.x + threadIdx.x;
    if (i < HASH_SIZE) { g_hkeys[i] = ~0ULL; g_hvals[i] = 0x7fffffff; }
}

__global__ void hash_insert_kernel(const int* __restrict__ coords,
                                   const int* __restrict__ batch_idx,
                                   int n, int coords_elems, int batch_elems) {
    int i = blockIdx.x * blockDim.x + threadIdx.x;
    if (i >= n) return;
    int c0 = (3 * i + 0 < coords_elems) ? coords[3 * i + 0] : 0;
    int c1 = (3 * i + 1 < coords_elems) ? coords[3 * i + 1] : 0;
    int c2 = (3 * i + 2 < coords_elems) ? coords[3 * i + 2] : 0;
    int b  = (i < batch_elems) ? batch_idx[i] : 0;
    long long x = (long long)c0 + (long long)b * 100000LL;
    unsigned long long key = ((unsigned long long)x << 40) |
                             ((unsigned long long)(long long)c1 << 20) |
                             ((unsigned long long)(long long)c2);
    unsigned s = hash_mix(key);
    for (int p = 0; p < MAX_PROBE; p++) {
        unsigned long long prev = atomicCAS(&g_hkeys[s & HASH_MASK], ~0ULL, key);
        if (prev == ~0ULL || prev == key) {
            atomicMin(&g_hvals[s & HASH_MASK], i);   // min-index tie-break
            return;
        }
        s = (s + 1) & HASH_MASK;
    }
}

__device__ __forceinline__ int hash_lookup(unsigned long long key, int n) {
    unsigned s = hash_mix(key);
    for (int p = 0; p < MAX_PROBE; p++) {
        unsigned long long k = g_hkeys[s & HASH_MASK];
        if (k == key) {
            int v = g_hvals[s & HASH_MASK];
            return (v >= 0 && v < n) ? v : -1;
        }
        if (k == ~0ULL) return -1;
        s = (s + 1) & HASH_MASK;
    }
    return -1;
}

// ---- precompute neighbor table (tile-major, matches conv smem layout) ----
__global__ void nbr_table_kernel(const int* __restrict__ coords,
                                 const int* __restrict__ batch_idx,
                                 int n, int ntiles,
                                 int coords_elems, int batch_elems) {
    int idx = blockIdx.x * blockDim.x + threadIdx.x;
    if (idx >= ntiles * 27 * 128) return;
    int tile = idx / 3456;
    int e    = idx % 3456;
    int k = e >> 7;
    int r = e & 127;
    int row = tile * 128 + r;
    int nb = -1;
    if (row < n) {
        int dx = (k / 9) - 1, dy = ((k / 3) % 3) - 1, dz = (k % 3) - 1;
        int c0 = (3 * row + 0 < coords_elems) ? coords[3 * row + 0] : 0;
        int c1 = (3 * row + 1 < coords_elems) ? coords[3 * row + 1] : 0;
        int c2 = (3 * row + 2 < coords_elems) ? coords[3 * row + 2] : 0;
        int b  = (row < batch_elems) ? batch_idx[row] : 0;
        long long x = (long long)c0 + (long long)b * 100000LL + dx;
        long long y = (long long)c1 + dy;
        long long z = (long long)c2 + dz;
        unsigned long long key = ((unsigned long long)x << 40) |
                                 ((unsigned long long)y << 20) |
                                 ((unsigned long long)z);
        nb = hash_lookup(key, n);
    }
    g_nbr[idx] = nb;
}

__global__ void zero_out_kernel(float* out, int nelem) {
    int i = blockIdx.x * blockDim.x + threadIdx.x;
    if (i < nelem) out[i] = 0.0f;
}

// ---- prep: split features into bf16 hi/lo (vectorized x4) ----
__global__ void feat_prep_kernel(const float4* __restrict__ feat4, int total4) {
    int i = blockIdx.x * blockDim.x + threadIdx.x;
    if (i >= total4) return;
    float4 x = feat4[i];
    __nv_bfloat16 h0 = __float2bfloat16(x.x);
    __nv_bfloat16 h1 = __float2bfloat16(x.y);
    __nv_bfloat16 h2 = __float2bfloat16(x.z);
    __nv_bfloat16 h3 = __float2bfloat16(x.w);
    __nv_bfloat16 l0 = __float2bfloat16(x.x - __bfloat162float(h0));
    __nv_bfloat16 l1 = __float2bfloat16(x.y - __bfloat162float(h1));
    __nv_bfloat16 l2 = __float2bfloat16(x.z - __bfloat162float(h2));
    __nv_bfloat16 l3 = __float2bfloat16(x.w - __bfloat162float(h3));
    unsigned hlo = ((unsigned)__bfloat16_as_ushort(h1) << 16) | __bfloat16_as_ushort(h0);
    unsigned hhi = ((unsigned)__bfloat16_as_ushort(h3) << 16) | __bfloat16_as_ushort(h2);
    unsigned llo = ((unsigned)__bfloat16_as_ushort(l1) << 16) | __bfloat16_as_ushort(l0);
    unsigned lhi = ((unsigned)__bfloat16_as_ushort(l3) << 16) | __bfloat16_as_ushort(l2);
    ((uint2*)g_Ahi4)[i] = make_uint2(hlo, hhi);
    ((uint2*)g_Alo4)[i] = make_uint2(llo, lhi);
}

#define SW128(off) ((off) ^ (((off) >> 3) & 0x70))

// ---- prep: transpose + split + pre-swizzle weights ----
__global__ void weight_prep_kernel(const float* __restrict__ weight, int welems) {
    int i = blockIdx.x * blockDim.x + threadIdx.x;   // 0 .. 27*4096-1
    if (i >= 27 * 4096) return;
    int k    = i >> 12;
    int cin  = (i >> 6) & 63;
    int cout = i & 63;
    float x = (i < welems) ? weight[i] : 0.0f;
    __nv_bfloat16 hi = __float2bfloat16(x);
    __nv_bfloat16 lo = __float2bfloat16(x - __bfloat162float(hi));
    unsigned off = SW128((unsigned)(cout * 128 + cin * 2));
    unsigned idx = ((unsigned)k * 8192 + off) >> 1;
    ((__nv_bfloat16*)g_Whi4)[idx] = hi;
    ((__nv_bfloat16*)g_Wlo4)[idx] = lo;
}

// ===========================================================================
// mma.sync conv kernel. One block = 128-row tile, 256 threads (8 warps).
// Warp grid 4(m) x 2(n). smem (dynamic, 3-stage):
//   A[3 stages][2 comps] 16KB each -> 0 .. 96K    (128 rows x 128B, SW128)
//   B[3 stages][2 comps]  8KB each -> 96K .. 144K (64 rows x 128B, SW128)
//   nbr 27*128 ints                -> 144K (13824B)
// Pipeline: prologue stages taps 0,1. Iter k: wait_group 1 (tap k landed) ->
//   sync -> stage tap k+2 into buf (k+2)%3 -> MMA tap k. Depth-2 prefetch.
// ===========================================================================

#define SM_A(buf, comp)  ((unsigned)(((buf) * 2 + (comp)) * 16384))
#define SM_B(buf, comp)  ((unsigned)(98304 + ((buf) * 2 + (comp)) * 8192))
#define SM_NBR           (147456u)
#define SMEM_TOTAL       (147456 + 13824)

__device__ __forceinline__ unsigned smem_u32(const void* p) {
    unsigned a;
    asm("{ .reg .u64 t; cvta.to.shared.u64 t, %1; cvt.u32.u64 %0, t; }"
        : "=r"(a) : "l"(p));
    return a;
}

__device__ __forceinline__ void ldsm_x4(unsigned addr, unsigned r[4]) {
    asm volatile("ldmatrix.sync.aligned.m8n8.x4.shared.b16 {%0,%1,%2,%3}, [%4];"
                 : "=r"(r[0]), "=r"(r[1]), "=r"(r[2]), "=r"(r[3]) : "r"(addr));
}

__global__ __launch_bounds__(256, 1)
void subm_conv_mma_kernel(float* __restrict__ out, int n) {
    extern __shared__ char smem[];
    const unsigned sbase = smem_u32(smem);
    const int tid  = threadIdx.x;
    const int wid  = tid >> 5;
    const int lane = tid & 31;
    const int tile = blockIdx.x;
    const int row0 = tile * 128;

    int* nbrS = (int*)(smem + SM_NBR);

    // ---- load precomputed neighbor table for this tile (linear, coalesced) --
    {
        const int* src = &g_nbr[tile * 3456];
        for (int e = tid; e < 3456; e += 256) nbrS[e] = src[e];
    }
    __syncthreads();

    const __nv_bfloat16* Ahi = (const __nv_bfloat16*)g_Ahi4;
    const __nv_bfloat16* Alo = (const __nv_bfloat16*)g_Alo4;

    // Async staging: A = gather (zero-fill masked rows), B = linear copy.
    // A: 2048 16B-chunks -> 8/thread. B: 1024 -> 4/thread. One commit group.
#define STAGE_TAP_ASYNC(kk, buf)                                              \
    {                                                                         \
        const int* nb_k = &nbrS[(kk) * 128];                                  \
        _Pragma("unroll")                                                     \
        for (int q = 0; q < 8; q++) {                                         \
            int e = tid + q * 256;                                            \
            int comp = e >> 10;                                               \
            int idx  = e & 1023;                                              \
            int r = idx >> 3, ch = idx & 7;                                   \
            int nb = nb_k[r];                                                 \
            const __nv_bfloat16* srcb = comp ? Alo : Ahi;                     \
            const void* gsrc = srcb + (size_t)(nb < 0 ? 0 : nb) * 64 + ch * 8;\
            unsigned ssize = (nb >= 0) ? 16u : 0u;                            \
            unsigned boff  = (unsigned)(r * 128 + ch * 16);                   \
            unsigned daddr = sbase + SM_A(buf, comp) + SW128(boff);           \
            asm volatile("cp.async.ca.shared.global [%0], [%1], 16, %2;"      \
                         :: "r"(daddr), "l"(gsrc), "r"(ssize) : "memory");    \
        }                                                                     \
        _Pragma("unroll")                                                     \
        for (int q = 0; q < 4; q++) {                                         \
            int e = tid + q * 256;                                            \
            int comp = e >> 9;                                                \
            int idx  = e & 511;                                               \
            const uint4* src = (comp ? g_Wlo4 : g_Whi4) + (kk) * 512 + idx;   \
            unsigned daddr = sbase + SM_B(buf, comp) + idx * 16;              \
            asm volatile("cp.async.ca.shared.global [%0], [%1], 16;"          \
                         :: "r"(daddr), "l"(src) : "memory");                 \
        }                                                                     \
        asm volatile("cp.async.commit_group;" ::: "memory");                  \
    }

    // prologue: depth-2 prefetch
    STAGE_TAP_ASYNC(0, 0)
    STAGE_TAP_ASYNC(1, 1)

    float acc[2][4][4];
#pragma unroll
    for (int t = 0; t < 2; t++)
#pragma unroll
        for (int j = 0; j < 4; j++)
#pragma unroll
            for (int c = 0; c < 4; c++) acc[t][j][c] = 0.0f;

    const int mrow0 = (wid >> 1) * 32;   // warp m-strip (0/32/64/96)
    const int nb0   = (wid & 1) * 32;    // warp n-half (0/32)

    const int a_row = lane & 15;
    const int a_kc  = lane >> 4;
    const int b_row = ((lane >> 4) << 3) + (lane & 7);
    const int b_kc  = (lane >> 3) & 1;

    int buf = 0;                 // k % 3, tracked incrementally
    for (int k = 0; k < 27; k++) {
        asm volatile("cp.async.wait_group 1;" ::: "memory");  // tap k landed
        __syncthreads();

        // stage tap k+2 into buf (k+2)%3; its last readers (compute k-1)
        // all passed the barrier above.
        int buf2 = buf + 2; if (buf2 >= 3) buf2 -= 3;
        if (k + 2 < 27) STAGE_TAP_ASYNC(k + 2, buf2)

        const unsigned a_hi = sbase + SM_A(buf, 0);
        const unsigned a_lo = sbase + SM_A(buf, 1);
        const unsigned b_hi = sbase + SM_B(buf, 0);
        const unsigned b_lo = sbase + SM_B(buf, 1);

#pragma unroll
        for (int kk = 0; kk < 4; kk++) {
            unsigned af[2][2][4];   // [comp][t]
            unsigned bf[2][2][4];   // [comp][nt]
#pragma unroll
            for (int t = 0; t < 2; t++) {
                unsigned boff = (unsigned)((mrow0 + t * 16 + a_row) * 128 +
                                           (kk * 2 + a_kc) * 16);
                ldsm_x4(a_hi + SW128(boff), af[0][t]);
                ldsm_x4(a_lo + SW128(boff), af[1][t]);
            }
#pragma unroll
            for (int nt = 0; nt < 2; nt++) {
                unsigned boff = (unsigned)((nb0 + nt * 16 + b_row) * 128 +
                                           (kk * 2 + b_kc) * 16);
                ldsm_x4(b_hi + SW128(boff), bf[0][nt]);
                ldsm_x4(b_lo + SW128(boff), bf[1][nt]);
            }
#pragma unroll
            for (int pair = 0; pair < 3; pair++) {
                const int ac = (pair == 2) ? 1 : 0;   // Ahi,Ahi,Alo
                const int bc = (pair == 1) ? 1 : 0;   // Whi,Wlo,Whi
#pragma unroll
                for (int t = 0; t < 2; t++)
#pragma unroll
                    for (int j = 0; j < 4; j++) {
                        asm volatile(
                            "mma.sync.aligned.m16n8k16.row.col.f32.bf16.bf16.f32 "
                            "{%0,%1,%2,%3}, {%4,%5,%6,%7}, {%8,%9}, {%0,%1,%2,%3};"
                            : "+f"(acc[t][j][0]), "+f"(acc[t][j][1]),
                              "+f"(acc[t][j][2]), "+f"(acc[t][j][3])
                            : "r"(af[ac][t][0]), "r"(af[ac][t][1]),
                              "r"(af[ac][t][2]), "r"(af[ac][t][3]),
                              "r"(bf[bc][j >> 1][(j & 1) * 2]),
                              "r"(bf[bc][j >> 1][(j & 1) * 2 + 1]));
                    }
            }
        }
        buf = buf + 1; if (buf >= 3) buf -= 3;
    }

    // ---- store: D frag rows = lane>>2 (+8), cols = (lane&3)*2 ----
    const int r_lo  = lane >> 2;
    const int c_off = (lane & 3) * 2;
#pragma unroll
    for (int t = 0; t < 2; t++)
#pragma unroll
        for (int j = 0; j < 4; j++) {
            int row = row0 + mrow0 + t * 16 + r_lo;
            int col = nb0 + j * 8 + c_off;
            if (row < n) {
                float2 v = make_float2(acc[t][j][0], acc[t][j][1]);
                *(float2*)(out + (size_t)row * 64 + col) = v;
            }
            if (row + 8 < n) {
                float2 v = make_float2(acc[t][j][2], acc[t][j][3]);
                *(float2*)(out + (size_t)(row + 8) * 64 + col) = v;
            }
        }
}

// ---------------------------------------------------------------------------
// Launch. Binding inferred from in_sizes ratios (unit-agnostic), as in R6.
// ---------------------------------------------------------------------------
extern "C" void kernel_launch(void* const* d_in, const int* in_sizes, int n_in,
                              void* d_out, int out_size) {
    float* out = (float*)d_out;

    int wi = -1;
    bool bytes_mode = false;
    for (int i = 0; i < n_in; i++) {
        if (in_sizes[i] == 27 * 64 * 64)          { wi = i; bytes_mode = false; }
        else if (in_sizes[i] == 27 * 64 * 64 * 4) { wi = i; bytes_mode = true;  }
    }
    int bi = -1, ci = -1, fi = -1;
    for (int b = 0; b < n_in && bi < 0; b++) {
        if (b == wi) continue;
        long long s = in_sizes[b];
        if (s <= 0) continue;
        int c = -1, f = -1;
        for (int j = 0; j < n_in; j++) {
            if (j == b || j == wi) continue;
            if ((long long)in_sizes[j] == s * 3)  c = j;
            if ((long long)in_sizes[j] == s * 64) f = j;
        }
        if (c >= 0 && f >= 0) { bi = b; ci = c; fi = f; }
    }

    if (wi < 0 || bi < 0) {
        int nelem = out_size > 0 ? out_size : 1;
        zero_out_kernel<<<(nelem + 255) / 256, 256>>>(out, nelem);
        return;
    }

    const int div          = bytes_mode ? 4 : 1;
    const int n            = in_sizes[bi] / div;
    const int batch_elems  = in_sizes[bi] / div;
    const int coords_elems = in_sizes[ci] / div;
    const int feat_elems   = in_sizes[fi] / div;
    const int weight_elems = in_sizes[wi] / div;

    if (n <= 0 || n > MAXN) {
        int nelem = out_size > 0 ? out_size : 1;
        zero_out_kernel<<<(nelem + 255) / 256, 256>>>(out, nelem);
        return;
    }

    const float* feat   = (const float*)d_in[fi];
    const int*   coords = (const int*)d_in[ci];
    const int*   batch  = (const int*)d_in[bi];
    const float* weight = (const float*)d_in[wi];

    // Idempotent, no static guards; non-stream API is capture-safe.
    cudaFuncSetAttribute(subm_conv_mma_kernel,
                         cudaFuncAttributeMaxDynamicSharedMemorySize,
                         SMEM_TOTAL);

    const int ntiles = (n + 127) / 128;
    const int feat4  = feat_elems / 4;
    const int nbr_total = ntiles * 3456;

    hash_init_kernel<<<(HASH_SIZE + 255) / 256, 256>>>();
    hash_insert_kernel<<<(n + 255) / 256, 256>>>(coords, batch, n,
                                                 coords_elems, batch_elems);
    feat_prep_kernel<<<(feat4 + 255) / 256, 256>>>((const float4*)feat, feat4);
    weight_prep_kernel<<<(27 * 4096 + 255) / 256, 256>>>(weight, weight_elems);
    nbr_table_kernel<<<(nbr_total + 255) / 256, 256>>>(coords, batch, n, ntiles,
                                                       coords_elems, batch_elems);
    subm_conv_mma_kernel<<<ntiles, 256, SMEM_TOTAL>>>(out, n);
}

// round 12
// speedup vs baseline: 1.9988x; 1.9988x over previous
#include <cuda_runtime.h>
#include <cuda_fp16.h>
#include <cstdint>

// ===========================================================================
// Submanifold 3x3x3 sparse conv, N~1e5, Cin=Cout=64, fp32 in/out.
// R12: single-pass fp16 mma.sync (m16n8k16) implicit GEMM.
//   out = sum_k gather_k(fp16(A)) @ fp16(W[k]),  f32 accumulate.
// fp16 quantization rel err ~3e-4 aggregate (threshold 1e-3).
// Structure = R10 (best known): in-kernel nbr, 2-buf cp.async pipeline.
// Baseline-PTX only (sm_100 target safe).
// ===========================================================================

#define HASH_BITS 18
#define HASH_SIZE (1u << HASH_BITS)
#define HASH_MASK (HASH_SIZE - 1u)
#define MAX_PROBE 4096
#define MAXN      131072

__device__ unsigned long long g_hkeys[HASH_SIZE];
__device__ int                g_hvals[HASH_SIZE];

// fp16 features: [MAXN][64]
__device__ uint4 g_Af4[MAXN * 64 * 2 / 16];
// fp16 transposed weights, PRE-SWIZZLED (SW128): tap k = 64 rows x 128B
__device__ uint4 g_Wf4[27 * 8192 / 16];

__device__ __forceinline__ unsigned hash_mix(unsigned long long z) {
    z ^= z >> 30; z *= 0xbf58476d1ce4e5b9ULL;
    z ^= z >> 27; z *= 0x94d049bb133111ebULL;
    z ^= z >> 31;
    return (unsigned)z & HASH_MASK;
}

__global__ void hash_init_kernel() {
    unsigned i = blockIdx.x * blockDim.x + threadIdx.x;
    if (i < HASH_SIZE) { g_hkeys[i] = ~0ULL; g_hvals[i] = 0x7fffffff; }
}

__global__ void hash_insert_kernel(const int* __restrict__ coords,
                                   const int* __restrict__ batch_idx,
                                   int n, int coords_elems, int batch_elems) {
    int i = blockIdx.x * blockDim.x + threadIdx.x;
    if (i >= n) return;
    int c0 = (3 * i + 0 < coords_elems) ? coords[3 * i + 0] : 0;
    int c1 = (3 * i + 1 < coords_elems) ? coords[3 * i + 1] : 0;
    int c2 = (3 * i + 2 < coords_elems) ? coords[3 * i + 2] : 0;
    int b  = (i < batch_elems) ? batch_idx[i] : 0;
    long long x = (long long)c0 + (long long)b * 100000LL;
    unsigned long long key = ((unsigned long long)x << 40) |
                             ((unsigned long long)(long long)c1 << 20) |
                             ((unsigned long long)(long long)c2);
    unsigned s = hash_mix(key);
    for (int p = 0; p < MAX_PROBE; p++) {
        unsigned long long prev = atomicCAS(&g_hkeys[s & HASH_MASK], ~0ULL, key);
        if (prev == ~0ULL || prev == key) {
            atomicMin(&g_hvals[s & HASH_MASK], i);   // min-index tie-break
            return;
        }
        s = (s + 1) & HASH_MASK;
    }
}

__device__ __forceinline__ int hash_lookup(unsigned long long key, int n) {
    unsigned s = hash_mix(key);
    for (int p = 0; p < MAX_PROBE; p++) {
        unsigned long long k = g_hkeys[s & HASH_MASK];
        if (k == key) {
            int v = g_hvals[s & HASH_MASK];
            return (v >= 0 && v < n) ? v : -1;
        }
        if (k == ~0ULL) return -1;
        s = (s + 1) & HASH_MASK;
    }
    return -1;
}

__global__ void zero_out_kernel(float* out, int nelem) {
    int i = blockIdx.x * blockDim.x + threadIdx.x;
    if (i < nelem) out[i] = 0.0f;
}

// ---- prep: features -> fp16 (vectorized x4) ----
__global__ void feat_prep_kernel(const float4* __restrict__ feat4, int total4) {
    int i = blockIdx.x * blockDim.x + threadIdx.x;
    if (i >= total4) return;
    float4 x = feat4[i];
    __half2 lo = __floats2half2_rn(x.x, x.y);
    __half2 hi = __floats2half2_rn(x.z, x.w);
    ((uint2*)g_Af4)[i] = make_uint2(*(unsigned*)&lo, *(unsigned*)&hi);
}

#define SW128(off) ((off) ^ (((off) >> 3) & 0x70))

// ---- prep: transpose + fp16 + pre-swizzle weights ----
// src W[k][cin][cout]; dst tap k: byte_off = cout*128 + cin*2, swizzled.
__global__ void weight_prep_kernel(const float* __restrict__ weight, int welems) {
    int i = blockIdx.x * blockDim.x + threadIdx.x;   // 0 .. 27*4096-1
    if (i >= 27 * 4096) return;
    int k    = i >> 12;
    int cin  = (i >> 6) & 63;
    int cout = i & 63;
    float x = (i < welems) ? weight[i] : 0.0f;
    __half h = __float2half_rn(x);
    unsigned off = SW128((unsigned)(cout * 128 + cin * 2));
    unsigned idx = ((unsigned)k * 8192 + off) >> 1;
    ((__half*)g_Wf4)[idx] = h;
}

// ===========================================================================
// mma.sync conv kernel. One block = 128-row tile, 256 threads (8 warps).
// Warp grid 4(m) x 2(n): warp w -> rows [(w>>1)*32,+32), cols [(w&1)*32,+32).
// smem (dynamic):
//   A[2 bufs] 16KB each -> 0 .. 32K     (128 rows x 128B, SW128)
//   B[2 bufs]  8KB each -> 32K .. 48K   (64 rows x 128B, SW128)
//   nbr 27*128 ints     -> 48K (13824B)   total 62976B -> occupancy 3
// Pipeline (R10): iter k: wait_group 0 -> sync -> stage(k+1, other buf)
//   -> mma(tap k) -> sync.
// ===========================================================================

#define SM_A(buf)  ((unsigned)((buf) * 16384))
#define SM_B(buf)  ((unsigned)(32768 + (buf) * 8192))
#define SM_NBR     (49152u)
#define SMEM_TOTAL (49152 + 13824)

__device__ __forceinline__ unsigned smem_u32(const void* p) {
    unsigned a;
    asm("{ .reg .u64 t; cvta.to.shared.u64 t, %1; cvt.u32.u64 %0, t; }"
        : "=r"(a) : "l"(p));
    return a;
}

__device__ __forceinline__ void ldsm_x4(unsigned addr, unsigned r[4]) {
    asm volatile("ldmatrix.sync.aligned.m8n8.x4.shared.b16 {%0,%1,%2,%3}, [%4];"
                 : "=r"(r[0]), "=r"(r[1]), "=r"(r[2]), "=r"(r[3]) : "r"(addr));
}

__global__ __launch_bounds__(256, 3)
void subm_conv_mma_kernel(const int*   __restrict__ coords,
                          const int*   __restrict__ batch_idx,
                          float*       __restrict__ out,
                          int n, int coords_elems, int batch_elems) {
    extern __shared__ char smem[];
    const unsigned sbase = smem_u32(smem);
    const int tid  = threadIdx.x;
    const int wid  = tid >> 5;
    const int lane = tid & 31;
    const int row0 = blockIdx.x * 128;

    int* nbrS = (int*)(smem + SM_NBR);

    // ---- neighbor table: 27 taps x 128 rows (clamped reads) ----
    for (int e = tid; e < 27 * 128; e += 256) {
        int k = e >> 7;
        int r = e & 127;
        int row = row0 + r;
        int nb = -1;
        if (row < n) {
            int dx = (k / 9) - 1, dy = ((k / 3) % 3) - 1, dz = (k % 3) - 1;
            int c0 = (3 * row + 0 < coords_elems) ? coords[3 * row + 0] : 0;
            int c1 = (3 * row + 1 < coords_elems) ? coords[3 * row + 1] : 0;
            int c2 = (3 * row + 2 < coords_elems) ? coords[3 * row + 2] : 0;
            int b  = (row < batch_elems) ? batch_idx[row] : 0;
            long long x = (long long)c0 + (long long)b * 100000LL + dx;
            long long y = (long long)c1 + dy;
            long long z = (long long)c2 + dz;
            unsigned long long key = ((unsigned long long)x << 40) |
                                     ((unsigned long long)y << 20) |
                                     ((unsigned long long)z);
            nb = hash_lookup(key, n);
        }
        nbrS[e] = nb;
    }
    __syncthreads();

    const __half* Af = (const __half*)g_Af4;

    // Async staging: A = gather (zero-fill masked rows), B = linear copy.
    // A: 1024 16B-chunks -> 4/thread. B: 512 -> 2/thread. One commit group.
#define STAGE_TAP_ASYNC(kk, buf)                                              \
    {                                                                         \
        const int* nb_k = &nbrS[(kk) * 128];                                  \
        _Pragma("unroll")                                                     \
        for (int q = 0; q < 4; q++) {                                         \
            int e = tid + q * 256;                                            \
            int r = e >> 3, ch = e & 7;                                       \
            int nb = nb_k[r];                                                 \
            const void* gsrc = Af + (size_t)(nb < 0 ? 0 : nb) * 64 + ch * 8;  \
            unsigned ssize = (nb >= 0) ? 16u : 0u;                            \
            unsigned boff  = (unsigned)(r * 128 + ch * 16);                   \
            unsigned daddr = sbase + SM_A(buf) + SW128(boff);                 \
            asm volatile("cp.async.ca.shared.global [%0], [%1], 16, %2;"      \
                         :: "r"(daddr), "l"(gsrc), "r"(ssize) : "memory");    \
        }                                                                     \
        _Pragma("unroll")                                                     \
        for (int q = 0; q < 2; q++) {                                         \
            int e = tid + q * 256;                                            \
            const uint4* src = g_Wf4 + (kk) * 512 + e;                        \
            unsigned daddr = sbase + SM_B(buf) + e * 16;                      \
            asm volatile("cp.async.ca.shared.global [%0], [%1], 16;"          \
                         :: "r"(daddr), "l"(src) : "memory");                 \
        }                                                                     \
        asm volatile("cp.async.commit_group;" ::: "memory");                  \
    }

    STAGE_TAP_ASYNC(0, 0)

    float acc[2][4][4];
#pragma unroll
    for (int t = 0; t < 2; t++)
#pragma unroll
        for (int j = 0; j < 4; j++)
#pragma unroll
            for (int c = 0; c < 4; c++) acc[t][j][c] = 0.0f;

    const int mrow0 = (wid >> 1) * 32;   // warp m-strip (0/32/64/96)
    const int nb0   = (wid & 1) * 32;    // warp n-half (0/32)

    const int a_row = lane & 15;          // A x4: rows 0-15 x 2 k-chunks
    const int a_kc  = lane >> 4;
    const int b_row = ((lane >> 4) << 3) + (lane & 7);   // B x4 n-rows
    const int b_kc  = (lane >> 3) & 1;

    for (int k = 0; k < 27; k++) {
        const int buf = k & 1;
        asm volatile("cp.async.wait_group 0;" ::: "memory");
        __syncthreads();   // tap k's smem visible to all warps

        // issue next tap's copies; they fly while we do MMA on tap k
        if (k + 1 < 27) STAGE_TAP_ASYNC(k + 1, (k + 1) & 1)

        const unsigned abase = sbase + SM_A(buf);
        const unsigned bbase = sbase + SM_B(buf);

#pragma unroll
        for (int kk = 0; kk < 4; kk++) {
            unsigned af[2][4];   // [t]
            unsigned bf[2][4];   // [nt]
#pragma unroll
            for (int t = 0; t < 2; t++) {
                unsigned boff = (unsigned)((mrow0 + t * 16 + a_row) * 128 +
                                           (kk * 2 + a_kc) * 16);
                ldsm_x4(abase + SW128(boff), af[t]);
            }
#pragma unroll
            for (int nt = 0; nt < 2; nt++) {
                unsigned boff = (unsigned)((nb0 + nt * 16 + b_row) * 128 +
                                           (kk * 2 + b_kc) * 16);
                ldsm_x4(bbase + SW128(boff), bf[nt]);
            }
#pragma unroll
            for (int t = 0; t < 2; t++)
#pragma unroll
                for (int j = 0; j < 4; j++) {
                    asm volatile(
                        "mma.sync.aligned.m16n8k16.row.col.f32.f16.f16.f32 "
                        "{%0,%1,%2,%3}, {%4,%5,%6,%7}, {%8,%9}, {%0,%1,%2,%3};"
                        : "+f"(acc[t][j][0]), "+f"(acc[t][j][1]),
                          "+f"(acc[t][j][2]), "+f"(acc[t][j][3])
                        : "r"(af[t][0]), "r"(af[t][1]),
                          "r"(af[t][2]), "r"(af[t][3]),
                          "r"(bf[j >> 1][(j & 1) * 2]),
                          "r"(bf[j >> 1][(j & 1) * 2 + 1]));
                }
        }
        __syncthreads();   // all warps done reading buf k before its reuse
    }

    // ---- store: D frag rows = lane>>2 (+8), cols = (lane&3)*2 ----
    const int r_lo  = lane >> 2;
    const int c_off = (lane & 3) * 2;
#pragma unroll
    for (int t = 0; t < 2; t++)
#pragma unroll
        for (int j = 0; j < 4; j++) {
            int row = row0 + mrow0 + t * 16 + r_lo;
            int col = nb0 + j * 8 + c_off;
            if (row < n) {
                float2 v = make_float2(acc[t][j][0], acc[t][j][1]);
                *(float2*)(out + (size_t)row * 64 + col) = v;
            }
            if (row + 8 < n) {
                float2 v = make_float2(acc[t][j][2], acc[t][j][3]);
                *(float2*)(out + (size_t)(row + 8) * 64 + col) = v;
            }
        }
}

// ---------------------------------------------------------------------------
// Launch. Binding inferred from in_sizes ratios (unit-agnostic), as in R6.
// ---------------------------------------------------------------------------
extern "C" void kernel_launch(void* const* d_in, const int* in_sizes, int n_in,
                              void* d_out, int out_size) {
    float* out = (float*)d_out;

    int wi = -1;
    bool bytes_mode = false;
    for (int i = 0; i < n_in; i++) {
        if (in_sizes[i] == 27 * 64 * 64)          { wi = i; bytes_mode = false; }
        else if (in_sizes[i] == 27 * 64 * 64 * 4) { wi = i; bytes_mode = true;  }
    }
    int bi = -1, ci = -1, fi = -1;
    for (int b = 0; b < n_in && bi < 0; b++) {
        if (b == wi) continue;
        long long s = in_sizes[b];
        if (s <= 0) continue;
        int c = -1, f = -1;
        for (int j = 0; j < n_in; j++) {
            if (j == b || j == wi) continue;
            if ((long long)in_sizes[j] == s * 3)  c = j;
            if ((long long)in_sizes[j] == s * 64) f = j;
        }
        if (c >= 0 && f >= 0) { bi = b; ci = c; fi = f; }
    }

    if (wi < 0 || bi < 0) {
        int nelem = out_size > 0 ? out_size : 1;
        zero_out_kernel<<<(nelem + 255) / 256, 256>>>(out, nelem);
        return;
    }

    const int div          = bytes_mode ? 4 : 1;
    const int n            = in_sizes[bi] / div;
    const int batch_elems  = in_sizes[bi] / div;
    const int coords_elems = in_sizes[ci] / div;
    const int feat_elems   = in_sizes[fi] / div;
    const int weight_elems = in_sizes[wi] / div;

    if (n <= 0 || n > MAXN) {
        int nelem = out_size > 0 ? out_size : 1;
        zero_out_kernel<<<(nelem + 255) / 256, 256>>>(out, nelem);
        return;
    }

    const float* feat   = (const float*)d_in[fi];
    const int*   coords = (const int*)d_in[ci];
    const int*   batch  = (const int*)d_in[bi];
    const float* weight = (const float*)d_in[wi];

    // Idempotent, no static guards; non-stream API is capture-safe.
    cudaFuncSetAttribute(subm_conv_mma_kernel,
                         cudaFuncAttributeMaxDynamicSharedMemorySize,
                         SMEM_TOTAL);

    const int feat4 = feat_elems / 4;   // feat_elems = n*64, divisible
    hash_init_kernel<<<(HASH_SIZE + 255) / 256, 256>>>();
    hash_insert_kernel<<<(n + 255) / 256, 256>>>(coords, batch, n,
                                                 coords_elems, batch_elems);
    feat_prep_kernel<<<(feat4 + 255) / 256, 256>>>((const float4*)feat, feat4);
    weight_prep_kernel<<<(27 * 4096 + 255) / 256, 256>>>(weight, weight_elems);
    subm_conv_mma_kernel<<<(n + 127) / 128, 256, SMEM_TOTAL>>>(
        coords, batch, out, n, coords_elems, batch_elems);
}